// round 1
// baseline (speedup 1.0000x reference)
#include <cuda_runtime.h>
#include <cuda_bf16.h>
#include <cstdint>

#define NMAX 100000
#define D 128

// Scratch (device globals: allocation-free per harness rules)
__device__ __align__(256) float g_agg[(size_t)NMAX * D];
__device__ __align__(256) float g_h[(size_t)NMAX * D];
__device__ int   g_deg[NMAX];
__device__ float g_inv[NMAX];
__device__ int   g_idx32;   // 1 if edge_index is int32, 0 if int64

// ---------------------------------------------------------------------------
// Detect edge-index dtype. int64 indices are < 1e5; int32 data read as u64
// has the next index in the high word -> value >= 2^32 (p(hi==0) ~ 1e-5/word).
__global__ void detect_kernel(const void* eidx) {
    const unsigned long long* p = (const unsigned long long*)eidx;
    int is32 = 0;
    #pragma unroll
    for (int i = 0; i < 4; i++)
        if (p[i] >= (1ULL << 32)) is32 = 1;
    g_idx32 = is32;
}

__device__ __forceinline__ int load_idx(const void* eidx, long long pos) {
    if (g_idx32) return ((const int*)eidx)[pos];
    return (int)(((const long long*)eidx)[pos]);
}

// ---------------------------------------------------------------------------
// Degree count: one thread per edge.
__global__ void deg_kernel(const void* eidx, int nE) {
    int e = blockIdx.x * blockDim.x + threadIdx.x;
    if (e >= nE) return;
    int dst = load_idx(eidx, (long long)nE + e);
    atomicAdd(&g_deg[dst], 1);
}

__global__ void inv_kernel(int nN) {
    int i = blockIdx.x * blockDim.x + threadIdx.x;
    if (i >= nN) return;
    int d = g_deg[i];
    g_inv[i] = 1.0f / (float)(d > 0 ? d : 1);
}

// ---------------------------------------------------------------------------
// Scatter-add: one warp per edge. Each lane handles one float4 (32 lanes x 4 = 128).
__global__ void scatter_kernel(const float4* __restrict__ feat, const void* eidx, int nE) {
    int gtid = blockIdx.x * blockDim.x + threadIdx.x;
    int e = gtid >> 5;
    int lane = gtid & 31;
    if (e >= nE) return;
    int src = load_idx(eidx, e);
    int dst = load_idx(eidx, (long long)nE + e);
    float4 v = feat[(size_t)src * 32 + lane];
    float* a = g_agg + (size_t)dst * D + lane * 4;
    asm volatile("red.global.add.v4.f32 [%0], {%1,%2,%3,%4};"
                 :: "l"(a), "f"(v.x), "f"(v.y), "f"(v.z), "f"(v.w) : "memory");
}

// ---------------------------------------------------------------------------
// Fused dual-GEMM: out[n,:] = (agg[n,:]*inv[n]) @ Wl + X[n,:] @ Wr + b  (+ReLU)
// Block: 64 rows x 128 cols, 256 threads. tx in [0,32): 4 cols; ty in [0,8): 8 rows.
// Both weight matrices resident in smem (128KB); A tiles 64KB. LDS pattern:
// W reads are 32 consecutive float4 per warp (conflict-free), A reads broadcast.
template <bool RELU>
__global__ void gemm_kernel(const float* __restrict__ X,
                            const float* __restrict__ Wl,
                            const float* __restrict__ Wr,
                            const float* __restrict__ bias,
                            float* __restrict__ out, int nN) {
    extern __shared__ float smem[];
    float* sWl = smem;            // 16384 floats
    float* sWr = smem + 16384;    // 16384
    float* sAm = smem + 32768;    // 8192 (mean rows)
    float* sAx = smem + 40960;    // 8192 (x rows)

    const int tid = threadIdx.x;
    const int m0 = blockIdx.x * 64;

    // Load both weight matrices (row-major [k][j], direct copy)
    {
        const float4* gl = (const float4*)Wl;
        const float4* gr = (const float4*)Wr;
        float4* sl = (float4*)sWl;
        float4* sr = (float4*)sWr;
        #pragma unroll
        for (int i = 0; i < 16; i++) {
            int idx = tid + i * 256;   // 4096 float4 per matrix
            sl[idx] = gl[idx];
            sr[idx] = gr[idx];
        }
    }
    // Load A tiles: 64 rows x 32 float4
    for (int i = tid; i < 64 * 32; i += 256) {
        int row = i >> 5, c = i & 31;
        int gr_ = m0 + row;
        float4 vm = make_float4(0.f, 0.f, 0.f, 0.f);
        float4 vx = vm;
        if (gr_ < nN) {
            float inv = g_inv[gr_];
            float4 a = ((const float4*)g_agg)[(size_t)gr_ * 32 + c];
            vm = make_float4(a.x * inv, a.y * inv, a.z * inv, a.w * inv);
            vx = ((const float4*)X)[(size_t)gr_ * 32 + c];
        }
        ((float4*)sAm)[i] = vm;
        ((float4*)sAx)[i] = vx;
    }
    __syncthreads();

    const int tx = tid & 31;   // col group: cols tx*4 .. tx*4+3
    const int ty = tid >> 5;   // row group: rows ty*8 .. ty*8+7

    float acc[8][4];
    #pragma unroll
    for (int r = 0; r < 8; r++)
        #pragma unroll
        for (int c = 0; c < 4; c++) acc[r][c] = 0.f;

    const float4* swl4 = (const float4*)sWl;
    const float4* swr4 = (const float4*)sWr;

    #pragma unroll 4
    for (int k = 0; k < 128; k++) {
        float4 wl = swl4[k * 32 + tx];
        float4 wr = swr4[k * 32 + tx];
        #pragma unroll
        for (int r = 0; r < 8; r++) {
            float am = sAm[(ty * 8 + r) * 128 + k];
            float ax = sAx[(ty * 8 + r) * 128 + k];
            acc[r][0] += am * wl.x + ax * wr.x;
            acc[r][1] += am * wl.y + ax * wr.y;
            acc[r][2] += am * wl.z + ax * wr.z;
            acc[r][3] += am * wl.w + ax * wr.w;
        }
    }

    float4 bb = ((const float4*)bias)[tx];
    #pragma unroll
    for (int r = 0; r < 8; r++) {
        int gr_ = m0 + ty * 8 + r;
        if (gr_ >= nN) continue;
        float4 o = make_float4(acc[r][0] + bb.x, acc[r][1] + bb.y,
                               acc[r][2] + bb.z, acc[r][3] + bb.w);
        if (RELU) {
            o.x = fmaxf(o.x, 0.f); o.y = fmaxf(o.y, 0.f);
            o.z = fmaxf(o.z, 0.f); o.w = fmaxf(o.w, 0.f);
        }
        ((float4*)out)[(size_t)gr_ * 32 + tx] = o;
    }
}

// ---------------------------------------------------------------------------
extern "C" void kernel_launch(void* const* d_in, const int* in_sizes, int n_in,
                              void* d_out, int out_size) {
    const float* x   = (const float*)d_in[0];
    const void*  eix = d_in[1];
    const float* Wl1 = (const float*)d_in[2];
    const float* Wr1 = (const float*)d_in[3];
    const float* b1  = (const float*)d_in[4];
    const float* Wl2 = (const float*)d_in[5];
    const float* Wr2 = (const float*)d_in[6];
    const float* b2  = (const float*)d_in[7];
    float* out = (float*)d_out;

    const int nN = in_sizes[0] / D;      // 100000
    const int nE = in_sizes[1] / 2;      // 1600000

    void *aggp, *degp, *hp;
    cudaGetSymbolAddress(&aggp, g_agg);
    cudaGetSymbolAddress(&degp, g_deg);
    cudaGetSymbolAddress(&hp,   g_h);
    float* h = (float*)hp;

    const size_t SMEM = 49152 * sizeof(float);  // 192 KB
    cudaFuncSetAttribute(gemm_kernel<true>,  cudaFuncAttributeMaxDynamicSharedMemorySize, (int)SMEM);
    cudaFuncSetAttribute(gemm_kernel<false>, cudaFuncAttributeMaxDynamicSharedMemorySize, (int)SMEM);

    const int scatterBlocks = (int)(((long long)nE * 32 + 255) / 256);
    const int gemmBlocks = (nN + 63) / 64;

    // degree (shared by both layers)
    cudaMemsetAsync(degp, 0, (size_t)nN * sizeof(int));
    detect_kernel<<<1, 1>>>(eix);
    deg_kernel<<<(nE + 255) / 256, 256>>>(eix, nE);
    inv_kernel<<<(nN + 255) / 256, 256>>>(nN);

    // ---- layer 1 ----
    cudaMemsetAsync(aggp, 0, (size_t)nN * D * sizeof(float));
    scatter_kernel<<<scatterBlocks, 256>>>((const float4*)x, eix, nE);
    gemm_kernel<true><<<gemmBlocks, 256, SMEM>>>(x, Wl1, Wr1, b1, h, nN);

    // ---- layer 2 ----
    cudaMemsetAsync(aggp, 0, (size_t)nN * D * sizeof(float));
    scatter_kernel<<<scatterBlocks, 256>>>((const float4*)h, eix, nE);
    gemm_kernel<false><<<gemmBlocks, 256, SMEM>>>(h, Wl2, Wr2, b2, out, nN);
}

// round 3
// speedup vs baseline: 1.3300x; 1.3300x over previous
#include <cuda_runtime.h>
#include <cuda_bf16.h>
#include <cstdint>

#define NMAX 100000
#define D 128

typedef unsigned long long ull;

// Scratch (device globals: allocation-free per harness rules)
__device__ __align__(256) float g_agg[(size_t)NMAX * D];   // mean-aggregated features
__device__ __align__(256) float g_h[(size_t)NMAX * D];     // layer-1 output
__device__ int   g_deg[NMAX];
__device__ int   g_off[NMAX + 1];
__device__ int   g_cur[NMAX];
__device__ int   g_esrc[1600000 + 1024];                   // src sorted by dst (CSR)
__device__ float g_inv[NMAX];
__device__ int   g_idx32;   // 1 if edge_index is int32, 0 if int64

// ---------------------------------------------------------------------------
// Detect edge-index dtype. int64 indices are < 1e5; int32 data read as u64
// has the next index in the high word -> value >= 2^32.
__global__ void detect_kernel(const void* eidx) {
    const unsigned long long* p = (const unsigned long long*)eidx;
    int is32 = 0;
    #pragma unroll
    for (int i = 0; i < 4; i++)
        if (p[i] >= (1ULL << 32)) is32 = 1;
    g_idx32 = is32;
}

__device__ __forceinline__ int load_idx(const void* eidx, long long pos) {
    if (g_idx32) return ((const int*)eidx)[pos];
    return (int)(((const long long*)eidx)[pos]);
}

// ---------------------------------------------------------------------------
__global__ void deg_kernel(const void* eidx, int nE) {
    int e = blockIdx.x * blockDim.x + threadIdx.x;
    if (e >= nE) return;
    int dst = load_idx(eidx, (long long)nE + e);
    atomicAdd(&g_deg[dst], 1);
}

// Single-block exclusive scan over degrees -> offsets, cursors, inv.
__global__ void scan_kernel(int nN, int nE) {
    __shared__ int part[1024];
    const int t = threadIdx.x;
    const int chunk = (nN + 1023) / 1024;
    const int start = t * chunk;
    const int end = min(start + chunk, nN);

    int s = 0;
    for (int i = start; i < end; i++) s += g_deg[i];
    part[t] = s;
    __syncthreads();
    // Hillis-Steele inclusive scan
    for (int off = 1; off < 1024; off <<= 1) {
        int v = (t >= off) ? part[t - off] : 0;
        __syncthreads();
        part[t] += v;
        __syncthreads();
    }
    int run = (t == 0) ? 0 : part[t - 1];
    for (int i = start; i < end; i++) {
        int d = g_deg[i];
        g_off[i] = run;
        g_cur[i] = run;
        g_inv[i] = 1.0f / (float)(d > 0 ? d : 1);
        run += d;
    }
    if (t == 0) g_off[nN] = nE;
}

// Bucket edges by dst: one thread per edge.
__global__ void fill_kernel(const void* eidx, int nE) {
    int e = blockIdx.x * blockDim.x + threadIdx.x;
    if (e >= nE) return;
    int src = load_idx(eidx, e);
    int dst = load_idx(eidx, (long long)nE + e);
    int p = atomicAdd(&g_cur[dst], 1);
    g_esrc[p] = src;
}

// ---------------------------------------------------------------------------
// Gather aggregation: one warp per node, lane handles one float4 (128 floats).
// Writes MEAN directly (inv applied). No atomics.
__global__ void agg_kernel(const float4* __restrict__ feat, int nN) {
    int gtid = blockIdx.x * blockDim.x + threadIdx.x;
    int w = gtid >> 5;
    int lane = gtid & 31;
    if (w >= nN) return;
    int beg = g_off[w], end = g_off[w + 1];
    float4 a0 = make_float4(0.f, 0.f, 0.f, 0.f);
    float4 a1 = a0;
    int i = beg;
    for (; i + 1 < end; i += 2) {
        int s0 = g_esrc[i], s1 = g_esrc[i + 1];
        float4 v0 = feat[(size_t)s0 * 32 + lane];
        float4 v1 = feat[(size_t)s1 * 32 + lane];
        a0.x += v0.x; a0.y += v0.y; a0.z += v0.z; a0.w += v0.w;
        a1.x += v1.x; a1.y += v1.y; a1.z += v1.z; a1.w += v1.w;
    }
    if (i < end) {
        int s0 = g_esrc[i];
        float4 v0 = feat[(size_t)s0 * 32 + lane];
        a0.x += v0.x; a0.y += v0.y; a0.z += v0.z; a0.w += v0.w;
    }
    float inv = g_inv[w];
    float4 o = make_float4((a0.x + a1.x) * inv, (a0.y + a1.y) * inv,
                           (a0.z + a1.z) * inv, (a0.w + a1.w) * inv);
    ((float4*)g_agg)[(size_t)w * 32 + lane] = o;
}

// ---------------------------------------------------------------------------
// Fused dual-GEMM with packed fp32x2 FMA:
//   out[n,:] = mean[n,:] @ Wl + X[n,:] @ Wr + b   (+ReLU)
// Block: 64 rows x 128 cols, 256 threads. Thread: 8 rows (4 row-pairs) x 4 cols.
// A tiles stored TRANSPOSED [k][row] with stride 66 so row-pairs are one
// aligned LDS.64 (uniform/broadcast). Accumulators packed over row-pairs.
#define AST 66   // transposed A stride (even -> 8B aligned pairs; limits conflicts)

template <bool RELU>
__global__ void __launch_bounds__(256, 1)
gemm_kernel(const float* __restrict__ X,
            const float* __restrict__ Wl,
            const float* __restrict__ Wr,
            const float* __restrict__ bias,
            float* __restrict__ out, int nN) {
    extern __shared__ float smem[];
    float* sWl  = smem;                 // 16384 floats
    float* sWr  = smem + 16384;         // 16384
    float* sAmT = smem + 32768;         // 128*66 = 8448 (transposed mean)
    float* sAxT = smem + 32768 + 8448;  // 8448 (transposed x)

    const int tid = threadIdx.x;
    const int m0 = blockIdx.x * 64;

    // Load both weight matrices (row-major [k][j])
    {
        const float4* gl = (const float4*)Wl;
        const float4* gr = (const float4*)Wr;
        float4* sl = (float4*)sWl;
        float4* sr = (float4*)sWr;
        #pragma unroll
        for (int i = 0; i < 16; i++) {
            int idx = tid + i * 256;
            sl[idx] = gl[idx];
            sr[idx] = gr[idx];
        }
    }
    // Load A tiles transposed: value (row,k) -> sA[k*AST + row]
    #pragma unroll
    for (int it = 0; it < 8; it++) {
        int i = tid + it * 256;            // 0..2047
        int row = i >> 5, c = i & 31;
        int gr_ = m0 + row;
        float4 vm = make_float4(0.f, 0.f, 0.f, 0.f);
        float4 vx = vm;
        if (gr_ < nN) {
            vm = ((const float4*)g_agg)[(size_t)gr_ * 32 + c];
            vx = ((const float4*)X)[(size_t)gr_ * 32 + c];
        }
        int k0 = c * 4;
        sAmT[(k0 + 0) * AST + row] = vm.x;
        sAmT[(k0 + 1) * AST + row] = vm.y;
        sAmT[(k0 + 2) * AST + row] = vm.z;
        sAmT[(k0 + 3) * AST + row] = vm.w;
        sAxT[(k0 + 0) * AST + row] = vx.x;
        sAxT[(k0 + 1) * AST + row] = vx.y;
        sAxT[(k0 + 2) * AST + row] = vx.z;
        sAxT[(k0 + 3) * AST + row] = vx.w;
    }
    __syncthreads();

    const int tx = tid & 31;   // cols tx*4 .. tx*4+3
    const int ty = tid >> 5;   // rows ty*8 .. ty*8+7

    // acc[rp][c] = packed {row 2rp, row 2rp+1} for column c
    ull acc[4][4];
    #pragma unroll
    for (int rp = 0; rp < 4; rp++)
        #pragma unroll
        for (int c = 0; c < 4; c++) acc[rp][c] = 0ULL;

    const uint4* swl4 = (const uint4*)sWl;
    const uint4* swr4 = (const uint4*)sWr;
    const int rbase = ty * 8;

    #pragma unroll 4
    for (int k = 0; k < 128; k++) {
        uint4 wl = swl4[k * 32 + tx];
        uint4 wr = swr4[k * 32 + tx];
        ull wld[4], wrd[4];
        asm("mov.b64 %0,{%1,%1};" : "=l"(wld[0]) : "r"(wl.x));
        asm("mov.b64 %0,{%1,%1};" : "=l"(wld[1]) : "r"(wl.y));
        asm("mov.b64 %0,{%1,%1};" : "=l"(wld[2]) : "r"(wl.z));
        asm("mov.b64 %0,{%1,%1};" : "=l"(wld[3]) : "r"(wl.w));
        asm("mov.b64 %0,{%1,%1};" : "=l"(wrd[0]) : "r"(wr.x));
        asm("mov.b64 %0,{%1,%1};" : "=l"(wrd[1]) : "r"(wr.y));
        asm("mov.b64 %0,{%1,%1};" : "=l"(wrd[2]) : "r"(wr.z));
        asm("mov.b64 %0,{%1,%1};" : "=l"(wrd[3]) : "r"(wr.w));

        const float* am_base = sAmT + k * AST + rbase;
        const float* ax_base = sAxT + k * AST + rbase;
        #pragma unroll
        for (int rp = 0; rp < 4; rp++) {
            ull am = *(const ull*)(am_base + 2 * rp);   // {mean[2rp], mean[2rp+1]}
            ull ax = *(const ull*)(ax_base + 2 * rp);
            #pragma unroll
            for (int c = 0; c < 4; c++) {
                asm("fma.rn.f32x2 %0,%1,%2,%0;" : "+l"(acc[rp][c]) : "l"(am), "l"(wld[c]));
                asm("fma.rn.f32x2 %0,%1,%2,%0;" : "+l"(acc[rp][c]) : "l"(ax), "l"(wrd[c]));
            }
        }
    }

    float4 bb = ((const float4*)bias)[tx];
    #pragma unroll
    for (int rp = 0; rp < 4; rp++) {
        float lo[4], hi[4];
        #pragma unroll
        for (int c = 0; c < 4; c++) {
            unsigned l_, h_;
            asm("mov.b64 {%0,%1},%2;" : "=r"(l_), "=r"(h_) : "l"(acc[rp][c]));
            lo[c] = __uint_as_float(l_);
            hi[c] = __uint_as_float(h_);
        }
        int g0 = m0 + rbase + 2 * rp;
        int g1 = g0 + 1;
        float4 o0 = make_float4(lo[0] + bb.x, lo[1] + bb.y, lo[2] + bb.z, lo[3] + bb.w);
        float4 o1 = make_float4(hi[0] + bb.x, hi[1] + bb.y, hi[2] + bb.z, hi[3] + bb.w);
        if (RELU) {
            o0.x = fmaxf(o0.x, 0.f); o0.y = fmaxf(o0.y, 0.f);
            o0.z = fmaxf(o0.z, 0.f); o0.w = fmaxf(o0.w, 0.f);
            o1.x = fmaxf(o1.x, 0.f); o1.y = fmaxf(o1.y, 0.f);
            o1.z = fmaxf(o1.z, 0.f); o1.w = fmaxf(o1.w, 0.f);
        }
        if (g0 < nN) ((float4*)out)[(size_t)g0 * 32 + tx] = o0;
        if (g1 < nN) ((float4*)out)[(size_t)g1 * 32 + tx] = o1;
    }
}

// ---------------------------------------------------------------------------
extern "C" void kernel_launch(void* const* d_in, const int* in_sizes, int n_in,
                              void* d_out, int out_size) {
    const float* x   = (const float*)d_in[0];
    const void*  eix = d_in[1];
    const float* Wl1 = (const float*)d_in[2];
    const float* Wr1 = (const float*)d_in[3];
    const float* b1  = (const float*)d_in[4];
    const float* Wl2 = (const float*)d_in[5];
    const float* Wr2 = (const float*)d_in[6];
    const float* b2  = (const float*)d_in[7];
    float* out = (float*)d_out;

    const int nN = in_sizes[0] / D;      // 100000
    const int nE = in_sizes[1] / 2;      // 1600000

    void *degp, *hp;
    cudaGetSymbolAddress(&degp, g_deg);
    cudaGetSymbolAddress(&hp,   g_h);
    float* h = (float*)hp;

    const size_t SMEM = (size_t)(16384 * 2 + 8448 * 2) * sizeof(float);  // ~194 KB
    cudaFuncSetAttribute(gemm_kernel<true>,  cudaFuncAttributeMaxDynamicSharedMemorySize, (int)SMEM);
    cudaFuncSetAttribute(gemm_kernel<false>, cudaFuncAttributeMaxDynamicSharedMemorySize, (int)SMEM);

    const int edgeBlocks = (nE + 255) / 256;
    const int aggBlocks  = (int)(((long long)nN * 32 + 255) / 256);
    const int gemmBlocks = (nN + 63) / 64;

    // ---- CSR build (shared by both layers) ----
    cudaMemsetAsync(degp, 0, (size_t)nN * sizeof(int));
    detect_kernel<<<1, 1>>>(eix);
    deg_kernel<<<edgeBlocks, 256>>>(eix, nE);
    scan_kernel<<<1, 1024>>>(nN, nE);
    fill_kernel<<<edgeBlocks, 256>>>(eix, nE);

    // ---- layer 1 ----
    agg_kernel<<<aggBlocks, 256>>>((const float4*)x, nN);
    gemm_kernel<true><<<gemmBlocks, 256, SMEM>>>(x, Wl1, Wr1, b1, h, nN);

    // ---- layer 2 ----
    agg_kernel<<<aggBlocks, 256>>>((const float4*)h, nN);
    gemm_kernel<false><<<gemmBlocks, 256, SMEM>>>(h, Wl2, Wr2, b2, out, nN);
}